// round 14
// baseline (speedup 1.0000x reference)
#include <cuda_runtime.h>
#include <cuda_bf16.h>
#include <math_constants.h>

// GaussianConditionalStanh: fused quantize(symbols) + dequantize.
//   y = inputs - means
//   idx = searchsorted(mid, y), side='left'  (count of mid < y)
//   out[0:N]  = (float)idx
//   out[N:2N] = codebook[idx] + means
//
// R13: R9/R10's exact single-probe affine search (runtime-verified;
// uniform binary-search fallback), 4x float4 per thread front-batched
// (8 independent LDG.128 -> deep DRAM queue), streaming cache ops.

#define L_CODE 60
#define NMID   59
#define VPT    4          // float4 vectors per thread

__device__ __forceinline__ int probe_idx(float y, const float* __restrict__ smid,
                                         float inv_step, float bias)
{
    int g = min(max(__float2int_rn(fmaf(y, inv_step, bias)), 0), NMID - 1);
    return g + (smid[g] < y);
}

__device__ __forceinline__ int bsearch_idx(float y, const float* __restrict__ smid)
{
    int i = 0;
    #pragma unroll
    for (int step = 32; step > 0; step >>= 1) {
        int n = i + step;
        if (n <= NMID && smid[n - 1] < y) i = n;
    }
    return i;
}

__global__ __launch_bounds__(256)
void gcs_kernel(const float4* __restrict__ x4,
                const float4* __restrict__ m4,
                const float*  __restrict__ codebook,
                float4* __restrict__ sym4,
                float4* __restrict__ dq4,
                int n4)
{
    __shared__ float sc[L_CODE];       // codebook values
    __shared__ float smid[NMID + 1];   // midpoints, smid[59] = +INF
    __shared__ int   sBad;

    if (threadIdx.x == 0) sBad = 0;
    if (threadIdx.x < L_CODE)
        sc[threadIdx.x] = codebook[threadIdx.x];
    __syncthreads();
    if (threadIdx.x < NMID)
        smid[threadIdx.x] = 0.5f * (sc[threadIdx.x] + sc[threadIdx.x + 1]);
    if (threadIdx.x == NMID)
        smid[NMID] = CUDART_INF_F;
    __syncthreads();

    const float m_lo = smid[0];
    const float inv_step = (float)(NMID - 1) / (smid[NMID - 1] - m_lo);
    const float bias = -m_lo * inv_step;   // u = y*inv_step + bias

    // Single-probe validity: |u_k - k| <= 0.497 for every midpoint.
    if (threadIdx.x < NMID) {
        float u = fmaf(smid[threadIdx.x], inv_step, bias);
        if (fabsf(u - (float)threadIdx.x) > 0.497f) sBad = 1;
    }
    __syncthreads();
    const bool fast = (sBad == 0);

    const int base = blockIdx.x * (blockDim.x * VPT) + threadIdx.x;
    const int last = base + (VPT - 1) * blockDim.x;

    if (fast && last < n4) {
        // Front-batch all 8 independent 128b streaming loads.
        float4 xv[VPT], mv[VPT];
        #pragma unroll
        for (int v = 0; v < VPT; v++) xv[v] = __ldcs(&x4[base + v * blockDim.x]);
        #pragma unroll
        for (int v = 0; v < VPT; v++) mv[v] = __ldcs(&m4[base + v * blockDim.x]);

        #pragma unroll
        for (int v = 0; v < VPT; v++) {
            float y0 = xv[v].x - mv[v].x;
            float y1 = xv[v].y - mv[v].y;
            float y2 = xv[v].z - mv[v].z;
            float y3 = xv[v].w - mv[v].w;

            int i0 = probe_idx(y0, smid, inv_step, bias);
            int i1 = probe_idx(y1, smid, inv_step, bias);
            int i2 = probe_idx(y2, smid, inv_step, bias);
            int i3 = probe_idx(y3, smid, inv_step, bias);

            float4 sv = make_float4((float)i0, (float)i1, (float)i2, (float)i3);
            float4 dv = make_float4(sc[i0] + mv[v].x, sc[i1] + mv[v].y,
                                    sc[i2] + mv[v].z, sc[i3] + mv[v].w);
            __stcs(&sym4[base + v * blockDim.x], sv);
            __stcs(&dq4[base + v * blockDim.x], dv);
        }
    } else {
        // General path: tail blocks and non-affine codebooks (exact).
        #pragma unroll
        for (int v = 0; v < VPT; v++) {
            int k = base + v * blockDim.x;
            if (k >= n4) break;
            float4 xv = __ldcs(&x4[k]);
            float4 mv = __ldcs(&m4[k]);
            float y0 = xv.x - mv.x, y1 = xv.y - mv.y;
            float y2 = xv.z - mv.z, y3 = xv.w - mv.w;
            int i0, i1, i2, i3;
            if (fast) {
                i0 = probe_idx(y0, smid, inv_step, bias);
                i1 = probe_idx(y1, smid, inv_step, bias);
                i2 = probe_idx(y2, smid, inv_step, bias);
                i3 = probe_idx(y3, smid, inv_step, bias);
            } else {
                i0 = bsearch_idx(y0, smid);
                i1 = bsearch_idx(y1, smid);
                i2 = bsearch_idx(y2, smid);
                i3 = bsearch_idx(y3, smid);
            }
            float4 sv = make_float4((float)i0, (float)i1, (float)i2, (float)i3);
            float4 dv = make_float4(sc[i0] + mv.x, sc[i1] + mv.y,
                                    sc[i2] + mv.z, sc[i3] + mv.w);
            __stcs(&sym4[k], sv);
            __stcs(&dq4[k], dv);
        }
    }
}

extern "C" void kernel_launch(void* const* d_in, const int* in_sizes, int n_in,
                              void* d_out, int out_size)
{
    const float* inputs   = (const float*)d_in[0];
    const float* means    = (const float*)d_in[1];
    const float* codebook = (const float*)d_in[2];
    float* out = (float*)d_out;

    int n  = in_sizes[0];      // 28,311,552
    int n4 = n / 4;            // 7,077,888

    float* sym = out;
    float* dq  = out + n;

    const int threads = 256;
    const int per_block = threads * VPT;             // 4 float4 per thread
    int blocks = (n4 + per_block - 1) / per_block;   // 6912 exact

    gcs_kernel<<<blocks, threads>>>(
        (const float4*)inputs, (const float4*)means, codebook,
        (float4*)sym, (float4*)dq, n4);
}